// round 8
// baseline (speedup 1.0000x reference)
#include <cuda_runtime.h>
#include <cuda_bf16.h>
#include <cstdint>

#define BB 1024
#define FF 4
#define MM 512
#define DD 8192
#define RITERS 10

// ---------------- device scratch (no allocations allowed) ----------------
__device__ __nv_bfloat16 g_inp[BB * DD];                  // 16 MB input signs
__device__ __nv_bfloat16 g_est[BB * FF * DD];             // 64 MB estimates (+-1)
__device__ __nv_bfloat16 g_X  [BB * FF * DD];             // 64 MB stage input
__device__ __nv_bfloat16 g_C1 [FF * MM * DD];             // 32 MB codebook signs [f][m][d]
// B2: tile-packed panels. panel p = f*64 + colTile (colTile = d>>7), 256KB each:
//     [chunk(16)][row(128) = d&127][kk(64)*2B]; chunks 0..7 hold +-128 plane (k<512), 8..15 the +-1 plane.
__device__ __nv_bfloat16 g_B2 [(size_t)FF * DD * 1024];   // 64 MB
// A2: tile-packed panels. panel q = f*8 + rowBlock (b>>7), 256KB each:
//     [chunk(16)][row(128) = b&127][kk(64)*2B]; chunks 0..7 = a-digits, 8..15 = b-digits.
__device__ __nv_bfloat16 g_A2 [BB * FF * 1024];           // 8 MB
__device__ float         g_sim[BB * FF * MM];             // 8 MB  final sim
__device__ int           g_notconv[RITERS];

#define PANEL_BYTES 262144   // 16 chunks * 128 rows * 128 B
#define CHUNK_BYTES 16384    // 128 rows * 128 B

__device__ __forceinline__ uint32_t sgn_bf16(float v) { return (v >= 0.f) ? 0x3F80u : 0xBF80u; }
__device__ __forceinline__ uint32_t bf16bits(int v) {
    __nv_bfloat16 h = __float2bfloat16((float)v);
    return (uint32_t)*reinterpret_cast<unsigned short*>(&h);
}

// ---------------- prep: reset + input/init cvt + codebook cvt ----------------
#define N_INP4 (BB * DD / 4)
#define N_EST4 (BB * FF * DD / 4)
#define NB_IE ((N_INP4 + N_EST4 + 255) / 256)
#define NB_CODE (16 * 256 * FF)

__global__ void k_prep(const float* __restrict__ inp, const float* __restrict__ init,
                       const float* __restrict__ code) {
    const int bid = blockIdx.x;
    const int tid = threadIdx.x;
    if (bid == 0 && tid < RITERS) g_notconv[tid] = 0;
    if (bid < NB_IE) {
        int t = bid * 256 + tid;
        if (t < N_INP4) {
            float4 v = ((const float4*)inp)[t];
            uint2 w;
            w.x = sgn_bf16(v.x) | (sgn_bf16(v.y) << 16);
            w.y = sgn_bf16(v.z) | (sgn_bf16(v.w) << 16);
            ((uint2*)g_inp)[t] = w;
        } else if (t < N_INP4 + N_EST4) {
            int u = t - N_INP4;
            float4 v = ((const float4*)init)[u];
            uint2 w;
            w.x = sgn_bf16(v.x) | (sgn_bf16(v.y) << 16);
            w.y = sgn_bf16(v.z) | (sgn_bf16(v.w) << 16);
            ((uint2*)g_est)[u] = w;
        }
    } else {
        // codebook -> C1 [f][m][d] signs AND tile-packed B2
        __shared__ unsigned short s[32][33];
        const int b2 = bid - NB_IE;
        const int m0 = (b2 & 15) * 32;
        const int d0 = ((b2 >> 4) & 255) * 32;
        const int f = b2 >> 12;
        const int tx = tid & 31;
        const int ty = tid >> 5;     // 0..7
#pragma unroll
        for (int r = 0; r < 4; r++) {
            int m = m0 + ty + r * 8;
            float v = code[((size_t)(f * MM + m)) * DD + d0 + tx];
            unsigned short sg = (v >= 0.f) ? 0x3F80u : 0xBF80u;
            s[ty + r * 8][tx] = sg;
            *(unsigned short*)&g_C1[((size_t)(f * MM + m)) * DD + d0 + tx] = sg;
        }
        __syncthreads();
        uint8_t* b2b = (uint8_t*)g_B2;
#pragma unroll
        for (int r = 0; r < 4; r++) {
            int d = d0 + ty + r * 8;
            unsigned short sg = s[tx][ty + r * 8];   // sign of C[f][m0+tx][d]
            unsigned short neg = sg >> 15;
            int k1 = m0 + tx;                        // 0..511
            size_t base = ((size_t)(f * 64 + (d >> 7))) * PANEL_BYTES
                        + (size_t)(d & 127) * 128 + (k1 & 63) * 2;
            *(unsigned short*)(b2b + base + (k1 >> 6) * CHUNK_BYTES)       = neg ? 0xC300u : 0x4300u; // +-128
            *(unsigned short*)(b2b + base + ((k1 >> 6) + 8) * CHUNK_BYTES) = sg;                       // +-1
        }
    }
}

// X[b][f][d] = input * prod_all * est_f  (sign-bit algebra on packed bf16 pairs)
__global__ void k_stage_x() {
    int t = blockIdx.x * blockDim.x + threadIdx.x;
    if (t >= BB * DD / 4) return;
    int b = t / (DD / 4);
    int dq = t % (DD / 4);
    const uint2* inp2 = (const uint2*)g_inp;
    const uint2* est2 = (const uint2*)g_est;
    uint2* x2 = (uint2*)g_X;
    uint2 wi = inp2[(size_t)b * (DD / 4) + dq];
    uint2 e[FF];
#pragma unroll
    for (int f = 0; f < FF; f++)
        e[f] = est2[((size_t)(b * FF + f)) * (DD / 4) + dq];
    uint32_t qx = wi.x ^ e[0].x ^ e[1].x ^ e[2].x ^ e[3].x;
    uint32_t qy = wi.y ^ e[0].y ^ e[1].y ^ e[2].y ^ e[3].y;
#pragma unroll
    for (int f = 0; f < FF; f++) {
        uint2 r;
        r.x = ((qx ^ e[f].x) & 0x80008000u) | 0x3F803F80u;
        r.y = ((qy ^ e[f].y) & 0x80008000u) | 0x3F803F80u;
        x2[((size_t)(b * FF + f)) * (DD / 4) + dq] = r;
    }
}

// ---------------- bf16 mma.sync GEMM, ldmatrix + 3-stage cp.async ----------------
// MODE 1: sim = X*C1^T   (K=8192), epilogue 128-split -> tile-packed g_A2
// MODE 2: sim = est*C1^T (K=8192), epilogue -> g_sim (float)
// MODE 3: Y  = A2*B2^T   (K=1024), persistent CTA sweeps 8 col tiles; linear panel loads;
//         epilogue sign -> g_est + conv flag
#define BLK_M 128
#define BLK_N 128
#define RSTRIDE 144                   // 64 bf16 = 128B data + 16B pad (LDSM conflict-free)
#define NSTAGE 3
#define A_SZ (BLK_M * RSTRIDE)
#define STG_SZ (2 * A_SZ)
#define SMEM_G (NSTAGE * STG_SZ)

__device__ __forceinline__ void mma_bf16(float* c, const uint32_t* a, const uint32_t* b) {
    asm volatile(
        "mma.sync.aligned.m16n8k16.row.col.f32.bf16.bf16.f32 "
        "{%0,%1,%2,%3}, {%4,%5,%6,%7}, {%8,%9}, {%0,%1,%2,%3};\n"
        : "+f"(c[0]), "+f"(c[1]), "+f"(c[2]), "+f"(c[3])
        : "r"(a[0]), "r"(a[1]), "r"(a[2]), "r"(a[3]), "r"(b[0]), "r"(b[1]));
}
__device__ __forceinline__ void ldsm4(uint32_t& r0, uint32_t& r1, uint32_t& r2, uint32_t& r3,
                                      uint32_t addr) {
    asm volatile("ldmatrix.sync.aligned.m8n8.x4.shared.b16 {%0,%1,%2,%3}, [%4];"
                 : "=r"(r0), "=r"(r1), "=r"(r2), "=r"(r3) : "r"(addr));
}

template <int MODE>
__global__ void __launch_bounds__(256, 2) k_gemm(int it) {
    constexpr int K = (MODE == 3) ? 1024 : DD;
    constexpr int KC = K / 64;
    constexpr int NT = (MODE == 3) ? 8 : 1;     // col tiles per CTA
    extern __shared__ char dsm[];
    __shared__ int sdiff;
    const int tid = threadIdx.x;
    const int lane = tid & 31;
    const int wid = tid >> 5;
    const int wm = wid >> 1, wn = wid & 1;      // 4x2 warps; warp tile 32x64
    int rowBase, f, colGroup = 0, colBase0 = 0;
    if (MODE == 3) { rowBase = blockIdx.x * BLK_M; f = blockIdx.y; colGroup = blockIdx.z; }
    else           { rowBase = blockIdx.y * BLK_M; colBase0 = blockIdx.x * BLK_N; f = blockIdx.z; }

    const char* Ap;
    const char* Bp = nullptr;
    size_t ldaB = 0, ldbB = 0;
    if (MODE == 1)      { Ap = (const char*)(g_X   + (size_t)f * DD);      ldaB = (size_t)FF * DD * 2;
                          Bp = (const char*)(g_C1  + (size_t)f * MM * DD); ldbB = (size_t)DD * 2; }
    else if (MODE == 2) { Ap = (const char*)(g_est + (size_t)f * DD);      ldaB = (size_t)FF * DD * 2;
                          Bp = (const char*)(g_C1  + (size_t)f * MM * DD); ldbB = (size_t)DD * 2; }
    else                { Ap = (const char*)g_A2 + ((size_t)(f * 8 + (rowBase >> 7))) * PANEL_BYTES; }

    if (tid == 0) sdiff = 0;

    const uint32_t smemBase = (uint32_t)__cvta_generic_to_shared(dsm);
    const uint32_t aoff = (wm * 32 + ((lane >> 3) & 1) * 8 + (lane & 7)) * RSTRIDE + (lane >> 4) * 16;
    const uint32_t boff = A_SZ + (wn * 64 + (lane >> 4) * 8 + (lane & 7)) * RSTRIDE + ((lane >> 3) & 1) * 16;

    auto load_stage = [&](int s, int c, const char* Bsrc, int colB) {
        char* ab = dsm + s * STG_SZ;
        char* bb = ab + A_SZ;
#pragma unroll
        for (int i = 0; i < 4; i++) {                 // A: 1024 chunks of 16B
            int cid = tid + i * 256;
            const char* g = (MODE == 3)
                ? Ap + (size_t)c * CHUNK_BYTES + (size_t)cid * 16
                : Ap + (size_t)(rowBase + (cid >> 3)) * ldaB + (size_t)c * 128 + (cid & 7) * 16;
            uint32_t sa = (uint32_t)__cvta_generic_to_shared(ab + (cid >> 3) * RSTRIDE + (cid & 7) * 16);
            asm volatile("cp.async.cg.shared.global [%0], [%1], 16;" :: "r"(sa), "l"(g));
        }
#pragma unroll
        for (int i = 0; i < 4; i++) {                 // B: 1024 chunks of 16B
            int cid = tid + i * 256;
            const char* g = (MODE == 3)
                ? Bsrc + (size_t)c * CHUNK_BYTES + (size_t)cid * 16
                : Bp + (size_t)(colB + (cid >> 3)) * ldbB + (size_t)c * 128 + (cid & 7) * 16;
            uint32_t sa = (uint32_t)__cvta_generic_to_shared(bb + (cid >> 3) * RSTRIDE + (cid & 7) * 16);
            asm volatile("cp.async.cg.shared.global [%0], [%1], 16;" :: "r"(sa), "l"(g));
        }
        asm volatile("cp.async.commit_group;");
    };

    int mydiff = 0;
#pragma unroll 1
    for (int tile = 0; tile < NT; tile++) {
        const int colBase = (MODE == 3) ? (colGroup * 1024 + tile * 128) : colBase0;
        const char* Bsrc = (MODE == 3)
            ? (const char*)g_B2 + ((size_t)(f * 64 + (colBase >> 7))) * PANEL_BYTES
            : nullptr;
        if (NT > 1) __syncthreads();    // protect stage buffers across tiles

        float acc[2][8][4];
#pragma unroll
        for (int mi = 0; mi < 2; mi++)
#pragma unroll
            for (int ni = 0; ni < 8; ni++)
#pragma unroll
                for (int j = 0; j < 4; j++) acc[mi][ni][j] = 0.f;

        load_stage(0, 0, Bsrc, colBase);
        load_stage(1, 1, Bsrc, colBase);
        int sc = 0, sl = 2;
#pragma unroll 1
        for (int c = 0; c < KC; c++) {
            if (c + 1 < KC) asm volatile("cp.async.wait_group 1;");
            else            asm volatile("cp.async.wait_group 0;");
            __syncthreads();
            const uint32_t sb = smemBase + sc * STG_SZ;
#pragma unroll
            for (int ks = 0; ks < 4; ks++) {
                const uint32_t co = ks * 32;
                uint32_t af[2][4], bf[8][2];
#pragma unroll
                for (int mi = 0; mi < 2; mi++)
                    ldsm4(af[mi][0], af[mi][1], af[mi][2], af[mi][3],
                          sb + aoff + mi * 16 * RSTRIDE + co);
#pragma unroll
                for (int p = 0; p < 4; p++)
                    ldsm4(bf[2 * p][0], bf[2 * p][1], bf[2 * p + 1][0], bf[2 * p + 1][1],
                          sb + boff + p * 16 * RSTRIDE + co);
#pragma unroll
                for (int mi = 0; mi < 2; mi++)
#pragma unroll
                    for (int ni = 0; ni < 8; ni++)
                        mma_bf16(acc[mi][ni], af[mi], bf[ni]);
            }
            if (c + 2 < KC) {
                load_stage(sl, c + 2, Bsrc, colBase);
                if (++sl == NSTAGE) sl = 0;
            }
            if (++sc == NSTAGE) sc = 0;
        }

        // ---------------- epilogue for this tile ----------------
#pragma unroll
        for (int mi = 0; mi < 2; mi++) {
#pragma unroll
            for (int ni = 0; ni < 8; ni++) {
                const int r0 = rowBase + wm * 32 + mi * 16 + (lane >> 2);
                const int c0 = colBase + wn * 64 + ni * 8 + (lane & 3) * 2;
#pragma unroll
                for (int h = 0; h < 2; h++) {
                    const int rr = r0 + h * 8;
                    const float v0 = acc[mi][ni][2 * h];
                    const float v1 = acc[mi][ni][2 * h + 1];
                    if (MODE == 1) {
                        int s0 = __float2int_rn(v0);
                        int s1 = __float2int_rn(v1);
                        int a0 = (s0 + 64) >> 7, b0 = s0 - (a0 << 7);
                        int a1 = (s1 + 64) >> 7, b1 = s1 - (a1 << 7);
                        // tile-packed A2: panel(f, rr>>7), chunk c0>>6 (digits a), +8 (digits b)
                        char* base = (char*)g_A2 + ((size_t)(f * 8 + (rr >> 7))) * PANEL_BYTES
                                   + (size_t)(c0 >> 6) * CHUNK_BYTES + (size_t)(rr & 127) * 128
                                   + (c0 & 63) * 2;
                        *(uint32_t*)base                       = bf16bits(a0) | (bf16bits(a1) << 16);
                        *(uint32_t*)(base + 8 * CHUNK_BYTES)   = bf16bits(b0) | (bf16bits(b1) << 16);
                    } else if (MODE == 2) {
                        *(float2*)(g_sim + ((size_t)rr * FF + f) * MM + c0) = make_float2(v0, v1);
                    } else {
                        uint32_t w = sgn_bf16(v0) | (sgn_bf16(v1) << 16);
                        uint32_t* ew = (uint32_t*)g_est + (((size_t)rr * FF + f) * DD + c0) / 2;
                        if (*ew != w) mydiff = 1;
                        *ew = w;
                    }
                }
            }
        }
    }
    if (MODE == 3) {
        if (mydiff) sdiff = 1;      // benign same-value race
        __syncthreads();
        if (tid == 0 && sdiff) atomicOr(&g_notconv[it], 1);
    }
}

// ---------------- finalize ----------------
__global__ void k_final(float* __restrict__ out) {
    int gt = blockIdx.x * blockDim.x + threadIdx.x;
    int w = gt >> 5;
    int lane = gt & 31;
    if (w < BB * FF) {
        const float* srow = g_sim + (size_t)w * MM;
        float bestv = -1.f;
        int bestm = 0;
#pragma unroll
        for (int j = 0; j < MM / 32; j++) {
            int m = j * 32 + lane;
            float v = fabsf(srow[m]);
            if (v > bestv) { bestv = v; bestm = m; }
        }
#pragma unroll
        for (int o = 16; o; o >>= 1) {
            float ov = __shfl_down_sync(0xFFFFFFFFu, bestv, o);
            int om = __shfl_down_sync(0xFFFFFFFFu, bestm, o);
            if (ov > bestv || (ov == bestv && om < bestm)) { bestv = ov; bestm = om; }
        }
        if (lane == 0) out[w] = (float)bestm;
    }
    if (blockIdx.x == 0 && threadIdx.x == 0) {
        int k = 0;
        bool done = false;
#pragma unroll
        for (int i = 0; i < RITERS; i++) {
            if (!done) k++;
            if (g_notconv[i] == 0) done = true;
        }
        out[BB * FF] = (float)k;
    }
}

// est (bf16 +-1) -> float out. Out base at float offset 4097 (only 4B aligned) -> scalar stores.
__global__ void k_est_out(float* __restrict__ out) {
    int t = blockIdx.x * blockDim.x + threadIdx.x;
    if (t >= BB * FF * DD / 4) return;
    uint2 w = ((const uint2*)g_est)[t];
    float* o = out + (size_t)(BB * FF) + 1 + (size_t)t * 4;
    o[0] = (w.x & 0x8000u) ? -1.f : 1.f;
    o[1] = (w.x & 0x80000000u) ? -1.f : 1.f;
    o[2] = (w.y & 0x8000u) ? -1.f : 1.f;
    o[3] = (w.y & 0x80000000u) ? -1.f : 1.f;
}

// ---------------- launch ----------------
extern "C" void kernel_launch(void* const* d_in, const int* in_sizes, int n_in,
                              void* d_out, int out_size) {
    const float* inp  = (const float*)d_in[0];
    const float* init = (const float*)d_in[1];
    const float* code = (const float*)d_in[2];
    float* out = (float*)d_out;

    cudaFuncSetAttribute((const void*)k_gemm<1>, cudaFuncAttributeMaxDynamicSharedMemorySize, SMEM_G);
    cudaFuncSetAttribute((const void*)k_gemm<2>, cudaFuncAttributeMaxDynamicSharedMemorySize, SMEM_G);
    cudaFuncSetAttribute((const void*)k_gemm<3>, cudaFuncAttributeMaxDynamicSharedMemorySize, SMEM_G);

    // Launch order puts iter0's k_gemm<3> at launch index 3 (the ncu capture slot).
    k_prep<<<NB_IE + NB_CODE, 256>>>(inp, init, code);                               // 0
    k_stage_x<<<(BB * DD / 4 + 255) / 256, 256>>>();                                 // 1
    k_gemm<1><<<dim3(MM / BLK_N, BB / BLK_M, FF), 256, SMEM_G>>>(0);                 // 2
    k_gemm<3><<<dim3(BB / BLK_M, FF, DD / 1024), 256, SMEM_G>>>(0);                  // 3 <- ncu

    for (int it = 1; it < RITERS; it++) {
        k_stage_x<<<(BB * DD / 4 + 255) / 256, 256>>>();
        k_gemm<1><<<dim3(MM / BLK_N, BB / BLK_M, FF), 256, SMEM_G>>>(0);
        k_gemm<3><<<dim3(BB / BLK_M, FF, DD / 1024), 256, SMEM_G>>>(it);
    }
    k_gemm<2><<<dim3(MM / BLK_N, BB / BLK_M, FF), 256, SMEM_G>>>(0);
    k_final<<<(BB * FF * 32 + 255) / 256, 256>>>(out);
    k_est_out<<<(BB * FF * DD / 4 + 255) / 256, 256>>>(out);
}

// round 10
// speedup vs baseline: 4.0426x; 4.0426x over previous
#include <cuda_runtime.h>
#include <cuda_bf16.h>
#include <cstdint>

#define BB 1024
#define FF 4
#define MM 512
#define DD 8192
#define RITERS 10

// ---------------- device scratch (no allocations allowed) ----------------
__device__ __nv_bfloat16 g_inp [BB * DD];                 // 16 MB input signs
__device__ __nv_bfloat16 g_est [BB * FF * DD];            // 64 MB estimates buffer A (parity 0)
__device__ __nv_bfloat16 g_est2[BB * FF * DD];            // 64 MB estimates buffer B (parity 1)
__device__ __nv_bfloat16 g_X  [BB * FF * DD];             // 64 MB stage input
__device__ __nv_bfloat16 g_C1 [FF * MM * DD];             // 32 MB codebook signs [f][m][d]
// B2: tile-packed panels. panel p = f*64 + colTile (colTile = d>>7), 256KB each:
//     [chunk(16)][row(128)=d&127][kk(64)*2B]; chunks 0..7: +-128 plane (k<512), 8..15: +-1 plane.
__device__ __nv_bfloat16 g_B2 [(size_t)FF * DD * 1024];   // 64 MB
// A2: tile-packed panels. panel q = f*8 + rowBlock (b>>7), 256KB each:
//     [chunk(16)][row(128)=b&127][kk(64)*2B]; chunks 0..7 = a-digits, 8..15 = b-digits.
__device__ __nv_bfloat16 g_A2 [BB * FF * 1024];           // 8 MB
__device__ float         g_sim[BB * FF * MM];             // 8 MB
__device__ int           g_notconv[RITERS];

#define PANEL_BYTES 262144   // 16 chunks * 128 rows * 128 B
#define CHUNK_BYTES 16384    // 128 rows * 128 B

__device__ __forceinline__ uint32_t sgn_bf16(float v) { return (v >= 0.f) ? 0x3F80u : 0xBF80u; }
__device__ __forceinline__ uint32_t bf16bits(int v) {
    __nv_bfloat16 h = __float2bfloat16((float)v);
    return (uint32_t)*reinterpret_cast<unsigned short*>(&h);
}

// ---------------- prep: reset + input/init cvt + codebook cvt ----------------
#define N_INP4 (BB * DD / 4)
#define N_EST4 (BB * FF * DD / 4)
#define NB_IE ((N_INP4 + N_EST4 + 255) / 256)
#define NB_CODE (16 * 256 * FF)

__global__ void k_prep(const float* __restrict__ inp, const float* __restrict__ init,
                       const float* __restrict__ code) {
    const int bid = blockIdx.x;
    const int tid = threadIdx.x;
    if (bid == 0 && tid < RITERS) g_notconv[tid] = 0;
    if (bid < NB_IE) {
        int t = bid * 256 + tid;
        if (t < N_INP4) {
            float4 v = ((const float4*)inp)[t];
            uint2 w;
            w.x = sgn_bf16(v.x) | (sgn_bf16(v.y) << 16);
            w.y = sgn_bf16(v.z) | (sgn_bf16(v.w) << 16);
            ((uint2*)g_inp)[t] = w;
        } else if (t < N_INP4 + N_EST4) {
            int u = t - N_INP4;
            float4 v = ((const float4*)init)[u];
            uint2 w;
            w.x = sgn_bf16(v.x) | (sgn_bf16(v.y) << 16);
            w.y = sgn_bf16(v.z) | (sgn_bf16(v.w) << 16);
            ((uint2*)g_est)[u] = w;
        }
    } else {
        __shared__ unsigned short s[32][33];
        const int b2 = bid - NB_IE;
        const int m0 = (b2 & 15) * 32;
        const int d0 = ((b2 >> 4) & 255) * 32;
        const int f = b2 >> 12;
        const int tx = tid & 31;
        const int ty = tid >> 5;
#pragma unroll
        for (int r = 0; r < 4; r++) {
            int m = m0 + ty + r * 8;
            float v = code[((size_t)(f * MM + m)) * DD + d0 + tx];
            unsigned short sg = (v >= 0.f) ? 0x3F80u : 0xBF80u;
            s[ty + r * 8][tx] = sg;
            *(unsigned short*)&g_C1[((size_t)(f * MM + m)) * DD + d0 + tx] = sg;
        }
        __syncthreads();
        uint8_t* b2b = (uint8_t*)g_B2;
#pragma unroll
        for (int r = 0; r < 4; r++) {
            int d = d0 + ty + r * 8;
            unsigned short sg = s[tx][ty + r * 8];
            unsigned short neg = sg >> 15;
            int k1 = m0 + tx;
            size_t base = ((size_t)(f * 64 + (d >> 7))) * PANEL_BYTES
                        + (size_t)(d & 127) * 128 + (k1 & 63) * 2;
            *(unsigned short*)(b2b + base + (k1 >> 6) * CHUNK_BYTES)       = neg ? 0xC300u : 0x4300u;
            *(unsigned short*)(b2b + base + ((k1 >> 6) + 8) * CHUNK_BYTES) = sg;
        }
    }
}

// X = input*prod*est_f from est[parity]; also conv-check est[parity] vs est[1-parity] -> notconv[it-1]
__global__ void k_stage_x(int it) {
    __shared__ int sflag;
    int t = blockIdx.x * blockDim.x + threadIdx.x;
    const int p = it & 1;
    const uint2* cur2 = (const uint2*)(p ? g_est2 : g_est);
    const uint2* old2 = (const uint2*)(p ? g_est : g_est2);
    if (threadIdx.x == 0) sflag = 0;
    __syncthreads();
    int b = t / (DD / 4);
    int dq = t % (DD / 4);
    const uint2* inp2 = (const uint2*)g_inp;
    uint2* x2 = (uint2*)g_X;
    uint2 wi = inp2[(size_t)b * (DD / 4) + dq];
    uint2 e[FF];
    uint32_t diff = 0;
#pragma unroll
    for (int f = 0; f < FF; f++) {
        size_t idx = ((size_t)(b * FF + f)) * (DD / 4) + dq;
        e[f] = cur2[idx];
        if (it > 0) {
            uint2 o = old2[idx];
            diff |= (e[f].x ^ o.x) | (e[f].y ^ o.y);
        }
    }
    uint32_t qx = wi.x ^ e[0].x ^ e[1].x ^ e[2].x ^ e[3].x;
    uint32_t qy = wi.y ^ e[0].y ^ e[1].y ^ e[2].y ^ e[3].y;
#pragma unroll
    for (int f = 0; f < FF; f++) {
        uint2 r;
        r.x = ((qx ^ e[f].x) & 0x80008000u) | 0x3F803F80u;
        r.y = ((qy ^ e[f].y) & 0x80008000u) | 0x3F803F80u;
        x2[((size_t)(b * FF + f)) * (DD / 4) + dq] = r;
    }
    if (it > 0) {
        if (diff) sflag = 1;      // benign same-value race
        __syncthreads();
        if (threadIdx.x == 0 && sflag) atomicOr(&g_notconv[it - 1], 1);
    }
}

// conv check for the last iteration: est(parity0) vs est2 -> notconv[9]
__global__ void k_conv9() {
    __shared__ int sflag;
    if (threadIdx.x == 0) sflag = 0;
    __syncthreads();
    int t = blockIdx.x * blockDim.x + threadIdx.x;
    uint2 a = ((const uint2*)g_est)[t];
    uint2 b = ((const uint2*)g_est2)[t];
    if ((a.x ^ b.x) | (a.y ^ b.y)) sflag = 1;
    __syncthreads();
    if (threadIdx.x == 0 && sflag) atomicOr(&g_notconv[RITERS - 1], 1);
}

// ---------------- bf16 mma.sync GEMM, ldmatrix + 3-stage cp.async ----------------
// MODE 1: sim = X*C1^T   (K=8192), epilogue 128-split -> tile-packed g_A2
// MODE 2: sim = est*C1^T (K=8192), epilogue -> g_sim
// MODE 3: Y  = A2*B2^T; persistent CTA, CONTINUOUS 128-chunk pipeline across 8 col tiles;
//         epilogue = pure packed sign stores into est[1 - (it&1)] (double buffer, no RMW)
#define BLK_M 128
#define BLK_N 128
#define RSTRIDE 144
#define NSTAGE 3
#define A_SZ (BLK_M * RSTRIDE)
#define STG_SZ (2 * A_SZ)
#define SMEM_G (NSTAGE * STG_SZ)

__device__ __forceinline__ void mma_bf16(float* c, const uint32_t* a, const uint32_t* b) {
    asm volatile(
        "mma.sync.aligned.m16n8k16.row.col.f32.bf16.bf16.f32 "
        "{%0,%1,%2,%3}, {%4,%5,%6,%7}, {%8,%9}, {%0,%1,%2,%3};\n"
        : "+f"(c[0]), "+f"(c[1]), "+f"(c[2]), "+f"(c[3])
        : "r"(a[0]), "r"(a[1]), "r"(a[2]), "r"(a[3]), "r"(b[0]), "r"(b[1]));
}
__device__ __forceinline__ void ldsm4(uint32_t& r0, uint32_t& r1, uint32_t& r2, uint32_t& r3,
                                      uint32_t addr) {
    asm volatile("ldmatrix.sync.aligned.m8n8.x4.shared.b16 {%0,%1,%2,%3}, [%4];"
                 : "=r"(r0), "=r"(r1), "=r"(r2), "=r"(r3) : "r"(addr));
}

template <int MODE>
__global__ void __launch_bounds__(256, 2) k_gemm(int it) {
    constexpr int KC = (MODE == 3) ? 16 : (DD / 64);  // chunks per tile
    constexpr int NT = (MODE == 3) ? 8 : 1;           // tiles per CTA
    constexpr int TOT = KC * NT;                      // total chunk stream length
    extern __shared__ char dsm[];
    const int tid = threadIdx.x;
    const int lane = tid & 31;
    const int wid = tid >> 5;
    const int wm = wid >> 1, wn = wid & 1;
    int rowBase, f, colGroup = 0, colBase0 = 0;
    if (MODE == 3) { rowBase = blockIdx.x * BLK_M; f = blockIdx.y; colGroup = blockIdx.z; }
    else           { rowBase = blockIdx.y * BLK_M; colBase0 = blockIdx.x * BLK_N; f = blockIdx.z; }

    const char* Ap;
    const char* Bp = nullptr;
    size_t ldaB = 0, ldbB = 0;
    if (MODE == 1)      { Ap = (const char*)(g_X   + (size_t)f * DD);      ldaB = (size_t)FF * DD * 2;
                          Bp = (const char*)(g_C1  + (size_t)f * MM * DD); ldbB = (size_t)DD * 2; }
    else if (MODE == 2) { Ap = (const char*)(g_est + (size_t)f * DD);      ldaB = (size_t)FF * DD * 2;
                          Bp = (const char*)(g_C1  + (size_t)f * MM * DD); ldbB = (size_t)DD * 2; }
    else                { Ap = (const char*)g_A2 + ((size_t)(f * 8 + (rowBase >> 7))) * PANEL_BYTES;
                          Bp = (const char*)g_B2 + ((size_t)(f * 64 + colGroup * 8)) * PANEL_BYTES; }
    __nv_bfloat16* estDst = (MODE == 3) ? ((it & 1) ? g_est : g_est2) : nullptr;

    const uint32_t smemBase = (uint32_t)__cvta_generic_to_shared(dsm);
    const uint32_t aoff = (wm * 32 + ((lane >> 3) & 1) * 8 + (lane & 7)) * RSTRIDE + (lane >> 4) * 16;
    const uint32_t boff = A_SZ + (wn * 64 + (lane >> 4) * 8 + (lane & 7)) * RSTRIDE + ((lane >> 3) & 1) * 16;

    // cc = global chunk index; for MODE 3: tile = cc>>4 (B panel), chunk = cc&15 (A cyclic)
    auto load_stage = [&](int s, int cc) {
        char* ab = dsm + s * STG_SZ;
        char* bb = ab + A_SZ;
#pragma unroll
        for (int i = 0; i < 4; i++) {
            int cid = tid + i * 256;
            const char* g = (MODE == 3)
                ? Ap + (size_t)(cc & 15) * CHUNK_BYTES + (size_t)cid * 16
                : Ap + (size_t)(rowBase + (cid >> 3)) * ldaB + (size_t)cc * 128 + (cid & 7) * 16;
            uint32_t sa = (uint32_t)__cvta_generic_to_shared(ab + (cid >> 3) * RSTRIDE + (cid & 7) * 16);
            asm volatile("cp.async.cg.shared.global [%0], [%1], 16;" :: "r"(sa), "l"(g));
        }
#pragma unroll
        for (int i = 0; i < 4; i++) {
            int cid = tid + i * 256;
            const char* g = (MODE == 3)
                ? Bp + (size_t)(cc >> 4) * PANEL_BYTES + (size_t)(cc & 15) * CHUNK_BYTES + (size_t)cid * 16
                : Bp + (size_t)(colBase0 + (cid >> 3)) * ldbB + (size_t)cc * 128 + (cid & 7) * 16;
            uint32_t sa = (uint32_t)__cvta_generic_to_shared(bb + (cid >> 3) * RSTRIDE + (cid & 7) * 16);
            asm volatile("cp.async.cg.shared.global [%0], [%1], 16;" :: "r"(sa), "l"(g));
        }
        asm volatile("cp.async.commit_group;");
    };

    load_stage(0, 0);
    load_stage(1, 1);
    int cc = 0, sl = 2;
#pragma unroll 1
    for (int tile = 0; tile < NT; tile++) {
        float acc[2][8][4];
#pragma unroll
        for (int mi = 0; mi < 2; mi++)
#pragma unroll
            for (int ni = 0; ni < 8; ni++)
#pragma unroll
                for (int j = 0; j < 4; j++) acc[mi][ni][j] = 0.f;

#pragma unroll 1
        for (int k = 0; k < KC; k++) {
            if (cc + 1 < TOT) asm volatile("cp.async.wait_group 1;");
            else              asm volatile("cp.async.wait_group 0;");
            __syncthreads();
            const uint32_t sb = smemBase + (cc % NSTAGE) * STG_SZ;
#pragma unroll
            for (int ks = 0; ks < 4; ks++) {
                const uint32_t co = ks * 32;
                uint32_t af[2][4], bf[8][2];
#pragma unroll
                for (int mi = 0; mi < 2; mi++)
                    ldsm4(af[mi][0], af[mi][1], af[mi][2], af[mi][3],
                          sb + aoff + mi * 16 * RSTRIDE + co);
#pragma unroll
                for (int p = 0; p < 4; p++)
                    ldsm4(bf[2 * p][0], bf[2 * p][1], bf[2 * p + 1][0], bf[2 * p + 1][1],
                          sb + boff + p * 16 * RSTRIDE + co);
#pragma unroll
                for (int mi = 0; mi < 2; mi++)
#pragma unroll
                    for (int ni = 0; ni < 8; ni++)
                        mma_bf16(acc[mi][ni], af[mi], bf[ni]);
            }
            if (cc + 2 < TOT) {
                load_stage(sl, cc + 2);
                if (++sl == NSTAGE) sl = 0;
            }
            cc++;
        }

        // ---------------- epilogue for this tile (pure stores; overlaps in-flight loads) ----
        const int colBase = (MODE == 3) ? (colGroup * 1024 + tile * 128) : colBase0;
#pragma unroll
        for (int mi = 0; mi < 2; mi++) {
#pragma unroll
            for (int ni = 0; ni < 8; ni++) {
                const int r0 = rowBase + wm * 32 + mi * 16 + (lane >> 2);
                const int c0 = colBase + wn * 64 + ni * 8 + (lane & 3) * 2;
#pragma unroll
                for (int h = 0; h < 2; h++) {
                    const int rr = r0 + h * 8;
                    const float v0 = acc[mi][ni][2 * h];
                    const float v1 = acc[mi][ni][2 * h + 1];
                    if (MODE == 1) {
                        int s0 = __float2int_rn(v0);
                        int s1 = __float2int_rn(v1);
                        int a0 = (s0 + 64) >> 7, b0 = s0 - (a0 << 7);
                        int a1 = (s1 + 64) >> 7, b1 = s1 - (a1 << 7);
                        char* base = (char*)g_A2 + ((size_t)(f * 8 + (rr >> 7))) * PANEL_BYTES
                                   + (size_t)(c0 >> 6) * CHUNK_BYTES + (size_t)(rr & 127) * 128
                                   + (c0 & 63) * 2;
                        *(uint32_t*)base                     = bf16bits(a0) | (bf16bits(a1) << 16);
                        *(uint32_t*)(base + 8 * CHUNK_BYTES) = bf16bits(b0) | (bf16bits(b1) << 16);
                    } else if (MODE == 2) {
                        *(float2*)(g_sim + ((size_t)rr * FF + f) * MM + c0) = make_float2(v0, v1);
                    } else {
                        uint32_t w = sgn_bf16(v0) | (sgn_bf16(v1) << 16);
                        *((uint32_t*)estDst + (((size_t)rr * FF + f) * DD + c0) / 2) = w;
                    }
                }
            }
        }
    }
}

// ---------------- finalize ----------------
__global__ void k_final(float* __restrict__ out) {
    int gt = blockIdx.x * blockDim.x + threadIdx.x;
    int w = gt >> 5;
    int lane = gt & 31;
    if (w < BB * FF) {
        const float* srow = g_sim + (size_t)w * MM;
        float bestv = -1.f;
        int bestm = 0;
#pragma unroll
        for (int j = 0; j < MM / 32; j++) {
            int m = j * 32 + lane;
            float v = fabsf(srow[m]);
            if (v > bestv) { bestv = v; bestm = m; }
        }
#pragma unroll
        for (int o = 16; o; o >>= 1) {
            float ov = __shfl_down_sync(0xFFFFFFFFu, bestv, o);
            int om = __shfl_down_sync(0xFFFFFFFFu, bestm, o);
            if (ov > bestv || (ov == bestv && om < bestm)) { bestv = ov; bestm = om; }
        }
        if (lane == 0) out[w] = (float)bestm;
    }
    if (blockIdx.x == 0 && threadIdx.x == 0) {
        int k = 0;
        bool done = false;
#pragma unroll
        for (int i = 0; i < RITERS; i++) {
            if (!done) k++;
            if (g_notconv[i] == 0) done = true;
        }
        out[BB * FF] = (float)k;
    }
}

// est (bf16 +-1, buffer A) -> float out. Base only 4B-aligned -> scalar stores.
__global__ void k_est_out(float* __restrict__ out) {
    int t = blockIdx.x * blockDim.x + threadIdx.x;
    if (t >= BB * FF * DD / 4) return;
    uint2 w = ((const uint2*)g_est)[t];
    float* o = out + (size_t)(BB * FF) + 1 + (size_t)t * 4;
    o[0] = (w.x & 0x8000u) ? -1.f : 1.f;
    o[1] = (w.x & 0x80000000u) ? -1.f : 1.f;
    o[2] = (w.y & 0x8000u) ? -1.f : 1.f;
    o[3] = (w.y & 0x80000000u) ? -1.f : 1.f;
}

// ---------------- launch ----------------
extern "C" void kernel_launch(void* const* d_in, const int* in_sizes, int n_in,
                              void* d_out, int out_size) {
    const float* inp  = (const float*)d_in[0];
    const float* init = (const float*)d_in[1];
    const float* code = (const float*)d_in[2];
    float* out = (float*)d_out;

    cudaFuncSetAttribute((const void*)k_gemm<1>, cudaFuncAttributeMaxDynamicSharedMemorySize, SMEM_G);
    cudaFuncSetAttribute((const void*)k_gemm<2>, cudaFuncAttributeMaxDynamicSharedMemorySize, SMEM_G);
    cudaFuncSetAttribute((const void*)k_gemm<3>, cudaFuncAttributeMaxDynamicSharedMemorySize, SMEM_G);

    // iter0's k_gemm<3> sits at launch index 3 (the ncu capture slot).
    k_prep<<<NB_IE + NB_CODE, 256>>>(inp, init, code);                               // 0
    k_stage_x<<<BB * DD / 4 / 256, 256>>>(0);                                        // 1
    k_gemm<1><<<dim3(MM / BLK_N, BB / BLK_M, FF), 256, SMEM_G>>>(0);                 // 2
    k_gemm<3><<<dim3(BB / BLK_M, FF, DD / 1024), 256, SMEM_G>>>(0);                  // 3 <- ncu

    for (int it = 1; it < RITERS; it++) {
        k_stage_x<<<BB * DD / 4 / 256, 256>>>(it);
        k_gemm<1><<<dim3(MM / BLK_N, BB / BLK_M, FF), 256, SMEM_G>>>(it);
        k_gemm<3><<<dim3(BB / BLK_M, FF, DD / 1024), 256, SMEM_G>>>(it);
    }
    k_conv9<<<BB * FF * DD / 4 / 256, 256>>>();
    k_gemm<2><<<dim3(MM / BLK_N, BB / BLK_M, FF), 256, SMEM_G>>>(0);
    k_final<<<(BB * FF * 32 + 255) / 256, 256>>>(out);
    k_est_out<<<(BB * FF * DD / 4 + 255) / 256, 256>>>(out);
}